// round 14
// baseline (speedup 1.0000x reference)
#include <cuda_runtime.h>
#include <cuda_fp16.h>
#include <cstdint>
#include <cstddef>

#define T_TOTAL 524288
#define NCHUNK  8192          // 64-row chunks
#define K1_BLK  4096          // k1: 128 rows (2 tiles) per CTA
#define K3_BLK  4096          // k3: 2 chunks per CTA
#define TILE_R  64
#define SUPER   128           // chunks per super-chunk in k2
#define NSUPER  (NCHUNK / SUPER)
#define SEGC    32            // chunks per segment (4 segments per super)

// packed per-row gate params, fp16: {f16x2(a0,a1), f16x2(b0,b1)} -> 134MB
__device__ __align__(16) uint2 g_ab[(size_t)T_TOTAL * 32];
// per-chunk aggregates and chunk-start states (fp32 exact path)
__device__ __align__(16) float g_Ac[NCHUNK * 64];
__device__ __align__(16) float g_Bc[NCHUNK * 64];
__device__ __align__(16) float g_U [NCHUNK * 64];
__device__ __align__(16) float g_A2[NSUPER * 64];
__device__ __align__(16) float g_B2[NSUPER * 64];

typedef unsigned long long u64;

__device__ __forceinline__ u64 pk2(float lo, float hi) {
    u64 r; asm("mov.b64 %0, {%1,%2};" : "=l"(r) : "f"(lo), "f"(hi)); return r;
}
__device__ __forceinline__ float2 upk(u64 v) {
    float2 r; asm("mov.b64 {%0,%1}, %2;" : "=f"(r.x), "=f"(r.y) : "l"(v)); return r;
}
__device__ __forceinline__ void ffma2(u64 &d, u64 a, u64 b) {
    asm("fma.rn.f32x2 %0, %1, %2, %0;" : "+l"(d) : "l"(a), "l"(b));
}
__device__ __forceinline__ float sigf(float x) {
    float e = __expf(-x);
    return __fdividef(1.0f, 1.0f + e);
}
__device__ __forceinline__ unsigned packh2(float x, float y) {
    unsigned r;
    asm("cvt.rn.f16x2.f32 %0, %2, %1;" : "=r"(r) : "f"(x), "f"(y));
    return r;
}
__device__ __forceinline__ float2 unpackh2(unsigned v) {
    float2 r;
    unsigned short lo = (unsigned short)(v & 0xFFFFu);
    unsigned short hi = (unsigned short)(v >> 16);
    asm("cvt.f32.f16 %0, %1;" : "=f"(r.x) : "h"(lo));
    asm("cvt.f32.f16 %0, %1;" : "=f"(r.y) : "h"(hi));
    return r;
}

// swizzled transposed x tile: float4 block (k, rb) at k*16 + (rb ^ (k&15))
__device__ __forceinline__ void fill_x(float* xsf, const float* __restrict__ inp,
                                       int t0, int tid) {
    #pragma unroll
    for (int p = 0; p < 4; p++) {
        int i = tid + p * 256;
        int r = i >> 4, c = i & 15;
        float4 v = *(const float4*)(inp + (size_t)(t0 + r) * 64 + 4 * c);
        int rb = r >> 2, r3 = r & 3;
        #pragma unroll
        for (int j = 0; j < 4; j++) {
            int k = 4 * c + j;
            float val = (j == 0) ? v.x : (j == 1) ? v.y : (j == 2) ? v.z : v.w;
            xsf[(k * 16 + (rb ^ (k & 15))) * 4 + r3] = val;
        }
    }
}

// GEMM1 core: 8 rows (4 packed pairs) x 4 channels per thread
__device__ __forceinline__ void gemm1_core(const float4* xs4, const float4* w4,
                                           int ri, int ci,
                                           u64 aL0[4], u64 aL1[4],
                                           u64 aR0[4], u64 aR1[4]) {
    const int rb0 = 2 * ri, rb1 = 2 * ri + 1;
    #pragma unroll
    for (int q = 0; q < 4; q++) { aL0[q]=0ull; aL1[q]=0ull; aR0[q]=0ull; aR1[q]=0ull; }
    #pragma unroll 1
    for (int k0 = 0; k0 < 64; k0 += 16) {
        #pragma unroll
        for (int j = 0; j < 16; j++) {
            const int k = k0 + j;
            ulonglong2 xA = *(const ulonglong2*)(xs4 + k * 16 + (rb0 ^ j));
            ulonglong2 xB = *(const ulonglong2*)(xs4 + k * 16 + (rb1 ^ j));
            float4 wv = w4[k * 32 + ci];
            u64 wl0 = pk2(wv.x, wv.x), wl1 = pk2(wv.y, wv.y);
            u64 wr0 = pk2(wv.z, wv.z), wr1 = pk2(wv.w, wv.w);
            ffma2(aL0[0], xA.x, wl0); ffma2(aL0[1], xA.y, wl0);
            ffma2(aL0[2], xB.x, wl0); ffma2(aL0[3], xB.y, wl0);
            ffma2(aL1[0], xA.x, wl1); ffma2(aL1[1], xA.y, wl1);
            ffma2(aL1[2], xB.x, wl1); ffma2(aL1[3], xB.y, wl1);
            ffma2(aR0[0], xA.x, wr0); ffma2(aR0[1], xA.y, wr0);
            ffma2(aR0[2], xB.x, wr0); ffma2(aR0[3], xB.y, wr0);
            ffma2(aR1[0], xA.x, wr1); ffma2(aR1[1], xA.y, wr1);
            ffma2(aR1[2], xB.x, wr1); ffma2(aR1[3], xB.y, wr1);
        }
    }
}

__device__ __forceinline__ void build_w1i(float4* W1i4, const float* __restrict__ W1, int tid) {
    #pragma unroll
    for (int p = 0; p < 8; p++) {
        int idx = tid + p * 256;
        int k = idx >> 5, cc = idx & 31;
        float2 l = *(const float2*)(W1 + k * 128 + 2 * cc);
        float2 r = *(const float2*)(W1 + k * 128 + 64 + 2 * cc);
        W1i4[idx] = make_float4(l.x, l.y, r.x, r.y);
    }
}

// ============================================================================
// k1: GEMM1 + gate -> g_ab (fp16 packed) + per-64-row-chunk aggregates (fp32)
// (identical to the 334us-passing version)
// ============================================================================
__global__ __launch_bounds__(256, 3)
void k1_gemm1(const float* __restrict__ inp,
              const float* __restrict__ W1,
              const float* __restrict__ B1) {
    extern __shared__ float sm[];
    float4* W1i4  = (float4*)sm;                 // [0,32768)
    float*  xsf   = sm + 8192;                   // [32768,49152)
    float2* parts = (float2*)(sm + 12288);       // [49152,53248)

    const int tid = threadIdx.x, c = blockIdx.x;
    const int ri = tid >> 5, ci = tid & 31;

    build_w1i(W1i4, W1, tid);
    const float bl0 = B1[2 * ci],      bl1 = B1[2 * ci + 1];
    const float br0 = B1[64 + 2 * ci], br1 = B1[64 + 2 * ci + 1];
    __syncthreads();

    #pragma unroll 1
    for (int tt = 0; tt < 2; tt++) {
        const int chunk = 2 * c + tt;
        const int t0 = chunk * TILE_R;
        fill_x(xsf, inp, t0, tid);
        __syncthreads();

        u64 aL0[4], aL1[4], aR0[4], aR1[4];
        gemm1_core((const float4*)xsf, W1i4, ri, ci, aL0, aL1, aR0, aR1);

        float A0 = 1.f, B0 = 0.f, A1 = 1.f, B1v = 0.f;
        #pragma unroll
        for (int p2 = 0; p2 < 4; p2++) {
            float2 L0 = upk(aL0[p2]), L1 = upk(aL1[p2]);
            float2 R0 = upk(aR0[p2]), R1 = upk(aR1[p2]);
            #pragma unroll
            for (int e = 0; e < 2; e++) {
                int r = 8 * ri + 2 * p2 + e;
                float l0 = sigf((e ? L0.y : L0.x) + bl0);
                float l1 = sigf((e ? L1.y : L1.x) + bl1);
                float r0 = sigf((e ? R0.y : R0.x) + br0);
                float r1 = sigf((e ? R1.y : R1.x) + br1);
                float a0 = l0 * r0, b0 = 1.f - l0;
                float a1 = l1 * r1, b1 = 1.f - l1;
                g_ab[(size_t)(t0 + r) * 32 + ci] =
                    make_uint2(packh2(a0, a1), packh2(b0, b1));
                B0  = fmaf(a0, B0, b0);  A0 *= a0;
                B1v = fmaf(a1, B1v, b1); A1 *= a1;
            }
        }
        ((float4*)parts)[ri * 32 + ci] = make_float4(A0, B0, A1, B1v);
        __syncthreads();

        if (tid < 64) {
            float Ac = 1.f, Bc = 0.f;
            #pragma unroll
            for (int g = 0; g < 8; g++) {
                float2 pp = parts[g * 64 + tid];
                Bc = fmaf(pp.x, Bc, pp.y);
                Ac *= pp.x;
            }
            g_Ac[chunk * 64 + tid] = Ac;
            g_Bc[chunk * 64 + tid] = Bc;
        }
        __syncthreads();
    }
}

// ============================================================================
// k2a: super aggregates — 4 segments x 64 channels per CTA, prefetched
// ============================================================================
__global__ __launch_bounds__(256, 8)
void k2a_super_agg() {
    __shared__ float2 parts[4 * 64];
    const int s = blockIdx.x;
    const int j = threadIdx.x & 63, seg = threadIdx.x >> 6;
    const int base = s * SUPER + seg * SEGC;

    float A = 1.f, B = 0.f;
    #pragma unroll 1
    for (int bq = 0; bq < SEGC / 8; bq++) {
        float a_[8], b_[8];
        #pragma unroll
        for (int i = 0; i < 8; i++) {
            a_[i] = g_Ac[(base + bq * 8 + i) * 64 + j];
            b_[i] = g_Bc[(base + bq * 8 + i) * 64 + j];
        }
        #pragma unroll
        for (int i = 0; i < 8; i++) { B = fmaf(a_[i], B, b_[i]); A *= a_[i]; }
    }
    parts[seg * 64 + j] = make_float2(A, B);
    __syncthreads();

    if (threadIdx.x < 64) {
        float As = 1.f, Bs = 0.f;
        #pragma unroll
        for (int g = 0; g < 4; g++) {
            float2 pp = parts[g * 64 + threadIdx.x];
            Bs = fmaf(pp.x, Bs, pp.y);
            As *= pp.x;
        }
        g_A2[s * 64 + threadIdx.x] = As;
        g_B2[s * 64 + threadIdx.x] = Bs;
    }
}

// ============================================================================
// k2c: super-scan (redundant per CTA, replaces k2b) + expand to chunk starts
// ============================================================================
__global__ __launch_bounds__(256, 8)
void k2c_expand() {
    __shared__ float2 parts[4 * 64];
    __shared__ float  segu [4 * 64];
    __shared__ float  supu [64];
    const int s = blockIdx.x;
    const int j = threadIdx.x & 63, seg = threadIdx.x >> 6;
    const int base = s * SUPER + seg * SEGC;

    // phase 0 (threads 0..63): super-start state = fold of supers 0..s-1
    if (threadIdx.x < 64) {
        float u = 0.f;
        #pragma unroll 1
        for (int s0 = 0; s0 < NSUPER; s0 += 16) {
            float A_[16], B_[16];
            #pragma unroll
            for (int i = 0; i < 16; i++) {
                int sp = s0 + i;                       // always < NSUPER: in-bounds
                float a = g_A2[sp * 64 + threadIdx.x];
                float b = g_B2[sp * 64 + threadIdx.x];
                A_[i] = (sp < s) ? a : 1.f;
                B_[i] = (sp < s) ? b : 0.f;
            }
            #pragma unroll
            for (int i = 0; i < 16; i++) { u = fmaf(A_[i], u, B_[i]); }
        }
        supu[threadIdx.x] = u;
    }

    // phase 1: segment aggregates
    float A = 1.f, B = 0.f;
    #pragma unroll 1
    for (int bq = 0; bq < SEGC / 8; bq++) {
        float a_[8], b_[8];
        #pragma unroll
        for (int i = 0; i < 8; i++) {
            a_[i] = g_Ac[(base + bq * 8 + i) * 64 + j];
            b_[i] = g_Bc[(base + bq * 8 + i) * 64 + j];
        }
        #pragma unroll
        for (int i = 0; i < 8; i++) { B = fmaf(a_[i], B, b_[i]); A *= a_[i]; }
    }
    parts[seg * 64 + j] = make_float2(A, B);
    __syncthreads();

    // phase 2: segment-start states from super-start
    if (threadIdx.x < 64) {
        float u = supu[threadIdx.x];
        #pragma unroll
        for (int g = 0; g < 4; g++) {
            segu[g * 64 + threadIdx.x] = u;
            float2 pp = parts[g * 64 + threadIdx.x];
            u = fmaf(pp.x, u, pp.y);
        }
    }
    __syncthreads();

    // phase 3: expand within segment
    float u = segu[seg * 64 + j];
    #pragma unroll 1
    for (int bq = 0; bq < SEGC / 8; bq++) {
        float a_[8], b_[8];
        #pragma unroll
        for (int i = 0; i < 8; i++) {
            a_[i] = g_Ac[(base + bq * 8 + i) * 64 + j];
            b_[i] = g_Bc[(base + bq * 8 + i) * 64 + j];
        }
        #pragma unroll
        for (int i = 0; i < 8; i++) {
            g_U[(base + bq * 8 + i) * 64 + j] = u;
            u = fmaf(a_[i], u, b_[i]);
        }
    }
}

// ============================================================================
// k3: dual-chunk — prefetch both chunks' fp16 a,b upfront, shared W2 fill
// ============================================================================
__global__ __launch_bounds__(256, 3)
void k3_replay_gemm2(const float* __restrict__ W2,
                     const float* __restrict__ B2,
                     float* __restrict__ out) {
    extern __shared__ float sm[];
    float*  zsf   = sm;                          // [0,16384)
    float2* parts = (float2*)(sm + 4096);        // [16384,20480)
    float*  ust   = sm + 5120;                   // [20480,22528)
    u64*    W2d   = (u64*)(sm + 5632);           // [22528,38912)

    const int tid = threadIdx.x, cb = blockIdx.x;
    const int ri = tid >> 5, ci = tid & 31;
    const int oc = tid & 31, rp = tid >> 5;
    const int c0 = 2 * cb, c1 = 2 * cb + 1;

    #pragma unroll
    for (int p = 0; p < 8; p++) {
        int idx = tid + p * 256;
        float w = W2[idx];
        W2d[idx] = pk2(w, w);
    }
    const float b2 = B2[oc];
    if (cb == 0 && tid < 32) out[tid] = B2[tid];   // row 0: z = 0

    // prefetch both chunks' packed fp16 a,b (high MLP)
    uint2 uv0[8], uv1[8];
    #pragma unroll
    for (int e = 0; e < 8; e++) {
        uv0[e] = g_ab[(size_t)(c0 * TILE_R + 8 * ri + e) * 32 + ci];
        uv1[e] = g_ab[(size_t)(c1 * TILE_R + 8 * ri + e) * 32 + ci];
    }
    float us0 = 0.f, us1 = 0.f;
    if (tid < 64) {
        us0 = g_U[c0 * 64 + tid];
        us1 = g_U[c1 * 64 + tid];
    }

    #pragma unroll 1
    for (int tt = 0; tt < 2; tt++) {
        const int t0 = (2 * cb + tt) * TILE_R;

        // unpack this chunk's a,b
        float4 ab[8];
        #pragma unroll
        for (int e = 0; e < 8; e++) {
            uint2 v = tt ? uv1[e] : uv0[e];
            float2 aa = unpackh2(v.x);
            float2 bb = unpackh2(v.y);
            ab[e] = make_float4(aa.x, aa.y, bb.x, bb.y);
        }

        // per-thread 8-row affine partial
        float A0 = 1.f, B0 = 0.f, A1 = 1.f, B1v = 0.f;
        #pragma unroll
        for (int e = 0; e < 8; e++) {
            B0  = fmaf(ab[e].x, B0,  ab[e].z);  A0 *= ab[e].x;
            B1v = fmaf(ab[e].y, B1v, ab[e].w);  A1 *= ab[e].y;
        }
        ((float4*)parts)[ri * 32 + ci] = make_float4(A0, B0, A1, B1v);
        __syncthreads();

        if (tid < 64) {
            float u = tt ? us1 : us0;
            #pragma unroll
            for (int g = 0; g < 8; g++) {
                ust[g * 64 + tid] = u;
                float2 pp = parts[g * 64 + tid];
                u = fmaf(pp.x, u, pp.y);
            }
        }
        __syncthreads();

        // register replay -> swizzled z tile
        {
            float2 us = *(const float2*)(ust + ri * 64 + 2 * ci);
            float u0 = us.x, u1 = us.y;
            const int j0 = 2 * ci, j1 = 2 * ci + 1;
            #pragma unroll
            for (int e = 0; e < 8; e++) {
                u0 = fmaf(ab[e].x, u0, ab[e].z);
                u1 = fmaf(ab[e].y, u1, ab[e].w);
                int r = 8 * ri + e;
                zsf[(j0 * 16 + ((r >> 2) ^ (j0 & 15))) * 4 + (r & 3)] = u0;
                zsf[(j1 * 16 + ((r >> 2) ^ (j1 & 15))) * 4 + (r & 3)] = u1;
            }
        }
        __syncthreads();

        // GEMM2: 8 rows (4 packed pairs) x 1 out channel per thread
        u64 acc0 = pk2(b2, b2), acc1 = acc0, acc2 = acc0, acc3 = acc0;
        {
            const int rb0 = 2 * rp, rb1 = 2 * rp + 1;
            const float4* zs4 = (const float4*)zsf;
            #pragma unroll 1
            for (int k0 = 0; k0 < 64; k0 += 16) {
                #pragma unroll
                for (int j = 0; j < 16; j++) {
                    const int k = k0 + j;
                    ulonglong2 zA = *(const ulonglong2*)(zs4 + k * 16 + (rb0 ^ j));
                    ulonglong2 zB = *(const ulonglong2*)(zs4 + k * 16 + (rb1 ^ j));
                    u64 wd = W2d[k * 32 + oc];
                    ffma2(acc0, zA.x, wd); ffma2(acc1, zA.y, wd);
                    ffma2(acc2, zB.x, wd); ffma2(acc3, zB.y, wd);
                }
            }
        }
        #pragma unroll
        for (int q = 0; q < 4; q++) {
            u64 a = (q == 0) ? acc0 : (q == 1) ? acc1 : (q == 2) ? acc2 : acc3;
            float2 v = upk(a);
            int t = t0 + 1 + 8 * rp + 2 * q;
            if (t < T_TOTAL)     out[(size_t)t * 32 + oc]       = v.x;
            if (t + 1 < T_TOTAL) out[(size_t)(t + 1) * 32 + oc] = v.y;
        }
        __syncthreads();   // protect zsf/parts reuse by next chunk
    }
}

// ============================================================================
// launch
// ============================================================================
extern "C" void kernel_launch(void* const* d_in, const int* in_sizes, int n_in,
                              void* d_out, int out_size) {
    const float* inp = (const float*)d_in[0];
    const float* W1  = (const float*)d_in[1];
    const float* B1  = (const float*)d_in[2];
    const float* W2  = (const float*)d_in[3];
    const float* B2  = (const float*)d_in[4];
    float* out = (float*)d_out;

    const int smem1 = 53248;
    const int smem3 = 38912;
    cudaFuncSetAttribute(k1_gemm1,        cudaFuncAttributeMaxDynamicSharedMemorySize, smem1);
    cudaFuncSetAttribute(k3_replay_gemm2, cudaFuncAttributeMaxDynamicSharedMemorySize, smem3);

    k1_gemm1<<<K1_BLK, 256, smem1>>>(inp, W1, B1);
    k2a_super_agg<<<NSUPER, 256>>>();
    k2c_expand<<<NSUPER, 256>>>();
    k3_replay_gemm2<<<K3_BLK, 256, smem3>>>(W2, B2, out);
    (void)in_sizes; (void)n_in; (void)out_size;
}

// round 15
// speedup vs baseline: 1.1350x; 1.1350x over previous
#include <cuda_runtime.h>
#include <cuda_fp16.h>
#include <cstdint>
#include <cstddef>

#define T_TOTAL 524288
#define NCHUNK  8192          // 64-row chunks
#define K1_BLK  4096          // k1: 128 rows (2 tiles) per CTA
#define TILE_R  64
#define SUPER   128           // chunks per super-chunk in k2
#define NSUPER  (NCHUNK / SUPER)
#define SEGC    32            // chunks per segment (4 segments per super)

// packed per-row gate params, fp16: {f16x2(a0,a1), f16x2(b0,b1)} -> 134MB
__device__ __align__(16) uint2 g_ab[(size_t)T_TOTAL * 32];
// per-chunk aggregates and chunk-start states (fp32 exact path)
__device__ __align__(16) float g_Ac[NCHUNK * 64];
__device__ __align__(16) float g_Bc[NCHUNK * 64];
__device__ __align__(16) float g_U [NCHUNK * 64];
__device__ __align__(16) float g_A2[NSUPER * 64];
__device__ __align__(16) float g_B2[NSUPER * 64];

typedef unsigned long long u64;

__device__ __forceinline__ u64 pk2(float lo, float hi) {
    u64 r; asm("mov.b64 %0, {%1,%2};" : "=l"(r) : "f"(lo), "f"(hi)); return r;
}
__device__ __forceinline__ float2 upk(u64 v) {
    float2 r; asm("mov.b64 {%0,%1}, %2;" : "=f"(r.x), "=f"(r.y) : "l"(v)); return r;
}
__device__ __forceinline__ void ffma2(u64 &d, u64 a, u64 b) {
    asm("fma.rn.f32x2 %0, %1, %2, %0;" : "+l"(d) : "l"(a), "l"(b));
}
__device__ __forceinline__ float sigf(float x) {
    float e = __expf(-x);
    return __fdividef(1.0f, 1.0f + e);
}
__device__ __forceinline__ unsigned packh2(float x, float y) {
    unsigned r;
    asm("cvt.rn.f16x2.f32 %0, %2, %1;" : "=r"(r) : "f"(x), "f"(y));
    return r;
}
__device__ __forceinline__ float2 unpackh2(unsigned v) {
    float2 r;
    unsigned short lo = (unsigned short)(v & 0xFFFFu);
    unsigned short hi = (unsigned short)(v >> 16);
    asm("cvt.f32.f16 %0, %1;" : "=f"(r.x) : "h"(lo));
    asm("cvt.f32.f16 %0, %1;" : "=f"(r.y) : "h"(hi));
    return r;
}

// swizzled transposed x tile: float4 block (k, rb) at k*16 + (rb ^ (k&15))
__device__ __forceinline__ void fill_x(float* xsf, const float* __restrict__ inp,
                                       int t0, int tid) {
    #pragma unroll
    for (int p = 0; p < 4; p++) {
        int i = tid + p * 256;
        int r = i >> 4, c = i & 15;
        float4 v = *(const float4*)(inp + (size_t)(t0 + r) * 64 + 4 * c);
        int rb = r >> 2, r3 = r & 3;
        #pragma unroll
        for (int j = 0; j < 4; j++) {
            int k = 4 * c + j;
            float val = (j == 0) ? v.x : (j == 1) ? v.y : (j == 2) ? v.z : v.w;
            xsf[(k * 16 + (rb ^ (k & 15))) * 4 + r3] = val;
        }
    }
}

// GEMM1 core: 8 rows (4 packed pairs) x 4 channels per thread
__device__ __forceinline__ void gemm1_core(const float4* xs4, const float4* w4,
                                           int ri, int ci,
                                           u64 aL0[4], u64 aL1[4],
                                           u64 aR0[4], u64 aR1[4]) {
    const int rb0 = 2 * ri, rb1 = 2 * ri + 1;
    #pragma unroll
    for (int q = 0; q < 4; q++) { aL0[q]=0ull; aL1[q]=0ull; aR0[q]=0ull; aR1[q]=0ull; }
    #pragma unroll 1
    for (int k0 = 0; k0 < 64; k0 += 16) {
        #pragma unroll
        for (int j = 0; j < 16; j++) {
            const int k = k0 + j;
            ulonglong2 xA = *(const ulonglong2*)(xs4 + k * 16 + (rb0 ^ j));
            ulonglong2 xB = *(const ulonglong2*)(xs4 + k * 16 + (rb1 ^ j));
            float4 wv = w4[k * 32 + ci];
            u64 wl0 = pk2(wv.x, wv.x), wl1 = pk2(wv.y, wv.y);
            u64 wr0 = pk2(wv.z, wv.z), wr1 = pk2(wv.w, wv.w);
            ffma2(aL0[0], xA.x, wl0); ffma2(aL0[1], xA.y, wl0);
            ffma2(aL0[2], xB.x, wl0); ffma2(aL0[3], xB.y, wl0);
            ffma2(aL1[0], xA.x, wl1); ffma2(aL1[1], xA.y, wl1);
            ffma2(aL1[2], xB.x, wl1); ffma2(aL1[3], xB.y, wl1);
            ffma2(aR0[0], xA.x, wr0); ffma2(aR0[1], xA.y, wr0);
            ffma2(aR0[2], xB.x, wr0); ffma2(aR0[3], xB.y, wr0);
            ffma2(aR1[0], xA.x, wr1); ffma2(aR1[1], xA.y, wr1);
            ffma2(aR1[2], xB.x, wr1); ffma2(aR1[3], xB.y, wr1);
        }
    }
}

__device__ __forceinline__ void build_w1i(float4* W1i4, const float* __restrict__ W1, int tid) {
    #pragma unroll
    for (int p = 0; p < 8; p++) {
        int idx = tid + p * 256;
        int k = idx >> 5, cc = idx & 31;
        float2 l = *(const float2*)(W1 + k * 128 + 2 * cc);
        float2 r = *(const float2*)(W1 + k * 128 + 64 + 2 * cc);
        W1i4[idx] = make_float4(l.x, l.y, r.x, r.y);
    }
}

// ============================================================================
// k1: GEMM1 + gate -> g_ab (fp16 packed) + per-64-row-chunk aggregates (fp32)
// (identical to the 334us-passing version)
// ============================================================================
__global__ __launch_bounds__(256, 3)
void k1_gemm1(const float* __restrict__ inp,
              const float* __restrict__ W1,
              const float* __restrict__ B1) {
    extern __shared__ float sm[];
    float4* W1i4  = (float4*)sm;                 // [0,32768)
    float*  xsf   = sm + 8192;                   // [32768,49152)
    float2* parts = (float2*)(sm + 12288);       // [49152,53248)

    const int tid = threadIdx.x, c = blockIdx.x;
    const int ri = tid >> 5, ci = tid & 31;

    build_w1i(W1i4, W1, tid);
    const float bl0 = B1[2 * ci],      bl1 = B1[2 * ci + 1];
    const float br0 = B1[64 + 2 * ci], br1 = B1[64 + 2 * ci + 1];
    __syncthreads();

    #pragma unroll 1
    for (int tt = 0; tt < 2; tt++) {
        const int chunk = 2 * c + tt;
        const int t0 = chunk * TILE_R;
        fill_x(xsf, inp, t0, tid);
        __syncthreads();

        u64 aL0[4], aL1[4], aR0[4], aR1[4];
        gemm1_core((const float4*)xsf, W1i4, ri, ci, aL0, aL1, aR0, aR1);

        float A0 = 1.f, B0 = 0.f, A1 = 1.f, B1v = 0.f;
        #pragma unroll
        for (int p2 = 0; p2 < 4; p2++) {
            float2 L0 = upk(aL0[p2]), L1 = upk(aL1[p2]);
            float2 R0 = upk(aR0[p2]), R1 = upk(aR1[p2]);
            #pragma unroll
            for (int e = 0; e < 2; e++) {
                int r = 8 * ri + 2 * p2 + e;
                float l0 = sigf((e ? L0.y : L0.x) + bl0);
                float l1 = sigf((e ? L1.y : L1.x) + bl1);
                float r0 = sigf((e ? R0.y : R0.x) + br0);
                float r1 = sigf((e ? R1.y : R1.x) + br1);
                float a0 = l0 * r0, b0 = 1.f - l0;
                float a1 = l1 * r1, b1 = 1.f - l1;
                g_ab[(size_t)(t0 + r) * 32 + ci] =
                    make_uint2(packh2(a0, a1), packh2(b0, b1));
                B0  = fmaf(a0, B0, b0);  A0 *= a0;
                B1v = fmaf(a1, B1v, b1); A1 *= a1;
            }
        }
        ((float4*)parts)[ri * 32 + ci] = make_float4(A0, B0, A1, B1v);
        __syncthreads();

        if (tid < 64) {
            float Ac = 1.f, Bc = 0.f;
            #pragma unroll
            for (int g = 0; g < 8; g++) {
                float2 pp = parts[g * 64 + tid];
                Bc = fmaf(pp.x, Bc, pp.y);
                Ac *= pp.x;
            }
            g_Ac[chunk * 64 + tid] = Ac;
            g_Bc[chunk * 64 + tid] = Bc;
        }
        __syncthreads();
    }
}

// ============================================================================
// k2a: super aggregates — 4 segments x 64 channels per CTA, prefetched
// ============================================================================
__global__ __launch_bounds__(256, 8)
void k2a_super_agg() {
    __shared__ float2 parts[4 * 64];
    const int s = blockIdx.x;
    const int j = threadIdx.x & 63, seg = threadIdx.x >> 6;
    const int base = s * SUPER + seg * SEGC;

    float A = 1.f, B = 0.f;
    #pragma unroll 1
    for (int bq = 0; bq < SEGC / 8; bq++) {
        float a_[8], b_[8];
        #pragma unroll
        for (int i = 0; i < 8; i++) {
            a_[i] = g_Ac[(base + bq * 8 + i) * 64 + j];
            b_[i] = g_Bc[(base + bq * 8 + i) * 64 + j];
        }
        #pragma unroll
        for (int i = 0; i < 8; i++) { B = fmaf(a_[i], B, b_[i]); A *= a_[i]; }
    }
    parts[seg * 64 + j] = make_float2(A, B);
    __syncthreads();

    if (threadIdx.x < 64) {
        float As = 1.f, Bs = 0.f;
        #pragma unroll
        for (int g = 0; g < 4; g++) {
            float2 pp = parts[g * 64 + threadIdx.x];
            Bs = fmaf(pp.x, Bs, pp.y);
            As *= pp.x;
        }
        g_A2[s * 64 + threadIdx.x] = As;
        g_B2[s * 64 + threadIdx.x] = Bs;
    }
}

// ============================================================================
// k2c: super-scan (redundant per CTA) + expand to chunk starts (merged k2b)
// ============================================================================
__global__ __launch_bounds__(256, 8)
void k2c_expand() {
    __shared__ float2 parts[4 * 64];
    __shared__ float  segu [4 * 64];
    __shared__ float  supu [64];
    const int s = blockIdx.x;
    const int j = threadIdx.x & 63, seg = threadIdx.x >> 6;
    const int base = s * SUPER + seg * SEGC;

    // phase 0 (threads 0..63): super-start state = fold of supers 0..s-1
    if (threadIdx.x < 64) {
        float u = 0.f;
        #pragma unroll 1
        for (int s0 = 0; s0 < NSUPER; s0 += 16) {
            float A_[16], B_[16];
            #pragma unroll
            for (int i = 0; i < 16; i++) {
                int sp = s0 + i;
                float a = g_A2[sp * 64 + threadIdx.x];
                float b = g_B2[sp * 64 + threadIdx.x];
                A_[i] = (sp < s) ? a : 1.f;
                B_[i] = (sp < s) ? b : 0.f;
            }
            #pragma unroll
            for (int i = 0; i < 16; i++) { u = fmaf(A_[i], u, B_[i]); }
        }
        supu[threadIdx.x] = u;
    }

    // phase 1: segment aggregates
    float A = 1.f, B = 0.f;
    #pragma unroll 1
    for (int bq = 0; bq < SEGC / 8; bq++) {
        float a_[8], b_[8];
        #pragma unroll
        for (int i = 0; i < 8; i++) {
            a_[i] = g_Ac[(base + bq * 8 + i) * 64 + j];
            b_[i] = g_Bc[(base + bq * 8 + i) * 64 + j];
        }
        #pragma unroll
        for (int i = 0; i < 8; i++) { B = fmaf(a_[i], B, b_[i]); A *= a_[i]; }
    }
    parts[seg * 64 + j] = make_float2(A, B);
    __syncthreads();

    // phase 2: segment-start states from super-start
    if (threadIdx.x < 64) {
        float u = supu[threadIdx.x];
        #pragma unroll
        for (int g = 0; g < 4; g++) {
            segu[g * 64 + threadIdx.x] = u;
            float2 pp = parts[g * 64 + threadIdx.x];
            u = fmaf(pp.x, u, pp.y);
        }
    }
    __syncthreads();

    // phase 3: expand within segment
    float u = segu[seg * 64 + j];
    #pragma unroll 1
    for (int bq = 0; bq < SEGC / 8; bq++) {
        float a_[8], b_[8];
        #pragma unroll
        for (int i = 0; i < 8; i++) {
            a_[i] = g_Ac[(base + bq * 8 + i) * 64 + j];
            b_[i] = g_Bc[(base + bq * 8 + i) * 64 + j];
        }
        #pragma unroll
        for (int i = 0; i < 8; i++) {
            g_U[(base + bq * 8 + i) * 64 + j] = u;
            u = fmaf(a_[i], u, b_[i]);
        }
    }
}

// ============================================================================
// k3: single-chunk; paired z stores (STS.64) + un-duplicated W2 (1-phase LDS)
// ============================================================================
__global__ __launch_bounds__(256, 4)
void k3_replay_gemm2(const float* __restrict__ W2,
                     const float* __restrict__ B2,
                     float* __restrict__ out) {
    extern __shared__ float sm[];
    float*  zsf   = sm;                          // [0,16384)
    float2* parts = (float2*)(sm + 4096);        // [16384,20480)
    float*  ust   = sm + 5120;                   // [20480,22528)
    float*  W2s   = sm + 5632;                   // [22528,30720): plain float

    const int tid = threadIdx.x, c = blockIdx.x;
    const int ri = tid >> 5, ci = tid & 31;
    const int oc = tid & 31, rp = tid >> 5;
    const int t0 = c * TILE_R;

    #pragma unroll
    for (int p = 0; p < 2; p++)          // W2s[k*32+oc] = W2[k][oc]
        ((float4*)W2s)[tid + p * 256] = ((const float4*)W2)[tid + p * 256];
    const float b2 = B2[oc];
    if (c == 0 && tid < 32) out[tid] = B2[tid];

    // load packed fp16 a,b for this thread's 8 rows x channel pair
    float4 ab[8];
    #pragma unroll
    for (int e = 0; e < 8; e++) {
        uint2 v = g_ab[(size_t)(t0 + 8 * ri + e) * 32 + ci];
        float2 aa = unpackh2(v.x);
        float2 bb = unpackh2(v.y);
        ab[e] = make_float4(aa.x, aa.y, bb.x, bb.y);
    }

    float A0 = 1.f, B0 = 0.f, A1 = 1.f, B1v = 0.f;
    #pragma unroll
    for (int e = 0; e < 8; e++) {
        B0  = fmaf(ab[e].x, B0,  ab[e].z);  A0 *= ab[e].x;
        B1v = fmaf(ab[e].y, B1v, ab[e].w);  A1 *= ab[e].y;
    }
    ((float4*)parts)[ri * 32 + ci] = make_float4(A0, B0, A1, B1v);
    __syncthreads();

    if (tid < 64) {
        float u = g_U[c * 64 + tid];
        #pragma unroll
        for (int g = 0; g < 8; g++) {
            ust[g * 64 + tid] = u;
            float2 pp = parts[g * 64 + tid];
            u = fmaf(pp.x, u, pp.y);
        }
    }
    __syncthreads();

    // register replay -> swizzled z tile, PAIRED row stores (STS.64)
    {
        float2 us = *(const float2*)(ust + ri * 64 + 2 * ci);
        float u0 = us.x, u1 = us.y;
        const int j0 = 2 * ci, j1 = 2 * ci + 1;
        #pragma unroll
        for (int p = 0; p < 4; p++) {
            float a0 = u0, a1 = u1;                       // row 2p value
            a0 = fmaf(ab[2*p].x,   u0, ab[2*p].z);
            a1 = fmaf(ab[2*p].y,   u1, ab[2*p].w);
            float c0 = fmaf(ab[2*p+1].x, a0, ab[2*p+1].z); // row 2p+1 value
            float c1 = fmaf(ab[2*p+1].y, a1, ab[2*p+1].w);
            u0 = c0; u1 = c1;
            int r = 8 * ri + 2 * p;                        // r&3 in {0,2}
            int rb = r >> 2, r3 = r & 3;
            *(u64*)(zsf + (j0 * 16 + (rb ^ (j0 & 15))) * 4 + r3) = pk2(a0, c0);
            *(u64*)(zsf + (j1 * 16 + (rb ^ (j1 & 15))) * 4 + r3) = pk2(a1, c1);
        }
    }
    __syncthreads();

    // GEMM2: 8 rows (4 packed pairs) x 1 out channel per thread
    u64 acc0 = pk2(b2, b2), acc1 = acc0, acc2 = acc0, acc3 = acc0;
    {
        const int rb0 = 2 * rp, rb1 = 2 * rp + 1;
        const float4* zs4 = (const float4*)zsf;
        #pragma unroll 1
        for (int k0 = 0; k0 < 64; k0 += 16) {
            #pragma unroll
            for (int j = 0; j < 16; j++) {
                const int k = k0 + j;
                ulonglong2 zA = *(const ulonglong2*)(zs4 + k * 16 + (rb0 ^ j));
                ulonglong2 zB = *(const ulonglong2*)(zs4 + k * 16 + (rb1 ^ j));
                float w = W2s[k * 32 + oc];                // 1-phase LDS.32
                u64 wd = pk2(w, w);                        // 1 MOV
                ffma2(acc0, zA.x, wd); ffma2(acc1, zA.y, wd);
                ffma2(acc2, zB.x, wd); ffma2(acc3, zB.y, wd);
            }
        }
    }
    #pragma unroll
    for (int q = 0; q < 4; q++) {
        u64 a = (q == 0) ? acc0 : (q == 1) ? acc1 : (q == 2) ? acc2 : acc3;
        float2 v = upk(a);
        int t = t0 + 1 + 8 * rp + 2 * q;
        if (t < T_TOTAL)     out[(size_t)t * 32 + oc]       = v.x;
        if (t + 1 < T_TOTAL) out[(size_t)(t + 1) * 32 + oc] = v.y;
    }
}

// ============================================================================
// launch
// ============================================================================
extern "C" void kernel_launch(void* const* d_in, const int* in_sizes, int n_in,
                              void* d_out, int out_size) {
    const float* inp = (const float*)d_in[0];
    const float* W1  = (const float*)d_in[1];
    const float* B1  = (const float*)d_in[2];
    const float* W2  = (const float*)d_in[3];
    const float* B2  = (const float*)d_in[4];
    float* out = (float*)d_out;

    const int smem1 = 53248;
    const int smem3 = 30720;
    cudaFuncSetAttribute(k1_gemm1,        cudaFuncAttributeMaxDynamicSharedMemorySize, smem1);
    cudaFuncSetAttribute(k3_replay_gemm2, cudaFuncAttributeMaxDynamicSharedMemorySize, smem3);

    k1_gemm1<<<K1_BLK, 256, smem1>>>(inp, W1, B1);
    k2a_super_agg<<<NSUPER, 256>>>();
    k2c_expand<<<NSUPER, 256>>>();
    k3_replay_gemm2<<<NCHUNK, 256, smem3>>>(W2, B2, out);
    (void)in_sizes; (void)n_in; (void)out_size;
}

// round 16
// speedup vs baseline: 1.2015x; 1.0586x over previous
#include <cuda_runtime.h>
#include <cuda_fp16.h>
#include <cstdint>
#include <cstddef>

#define T_TOTAL 524288
#define NCHUNK  8192          // 64-row chunks
#define K1_BLK  4096          // k1: 128 rows (2 tiles) per CTA
#define TILE_R  64
#define SUPER   128           // chunks per super-chunk in k2
#define NSUPER  (NCHUNK / SUPER)
#define SEGC    32            // chunks per segment (4 segments per super)

// packed per-row gate params, fp16: {f16x2(a0,a1), f16x2(b0,b1)} -> 134MB
__device__ __align__(16) uint2 g_ab[(size_t)T_TOTAL * 32];
// per-chunk aggregates and chunk-start states (fp32 exact path)
__device__ __align__(16) float g_Ac[NCHUNK * 64];
__device__ __align__(16) float g_Bc[NCHUNK * 64];
__device__ __align__(16) float g_U [NCHUNK * 64];
__device__ __align__(16) float g_A2[NSUPER * 64];
__device__ __align__(16) float g_B2[NSUPER * 64];

typedef unsigned long long u64;

__device__ __forceinline__ u64 pk2(float lo, float hi) {
    u64 r; asm("mov.b64 %0, {%1,%2};" : "=l"(r) : "f"(lo), "f"(hi)); return r;
}
__device__ __forceinline__ float2 upk(u64 v) {
    float2 r; asm("mov.b64 {%0,%1}, %2;" : "=f"(r.x), "=f"(r.y) : "l"(v)); return r;
}
__device__ __forceinline__ void ffma2(u64 &d, u64 a, u64 b) {
    asm("fma.rn.f32x2 %0, %1, %2, %0;" : "+l"(d) : "l"(a), "l"(b));
}
__device__ __forceinline__ float sigf(float x) {
    float e = __expf(-x);
    return __fdividef(1.0f, 1.0f + e);
}
__device__ __forceinline__ unsigned packh2(float x, float y) {
    unsigned r;
    asm("cvt.rn.f16x2.f32 %0, %2, %1;" : "=r"(r) : "f"(x), "f"(y));
    return r;
}
__device__ __forceinline__ float2 unpackh2(unsigned v) {
    float2 r;
    unsigned short lo = (unsigned short)(v & 0xFFFFu);
    unsigned short hi = (unsigned short)(v >> 16);
    asm("cvt.f32.f16 %0, %1;" : "=f"(r.x) : "h"(lo));
    asm("cvt.f32.f16 %0, %1;" : "=f"(r.y) : "h"(hi));
    return r;
}

// swizzled transposed x tile: float4 block (k, rb) at k*16 + (rb ^ (k&15))
__device__ __forceinline__ void fill_x(float* xsf, const float* __restrict__ inp,
                                       int t0, int tid) {
    #pragma unroll
    for (int p = 0; p < 4; p++) {
        int i = tid + p * 256;
        int r = i >> 4, c = i & 15;
        float4 v = *(const float4*)(inp + (size_t)(t0 + r) * 64 + 4 * c);
        int rb = r >> 2, r3 = r & 3;
        #pragma unroll
        for (int j = 0; j < 4; j++) {
            int k = 4 * c + j;
            float val = (j == 0) ? v.x : (j == 1) ? v.y : (j == 2) ? v.z : v.w;
            xsf[(k * 16 + (rb ^ (k & 15))) * 4 + r3] = val;
        }
    }
}

// GEMM1 core: 8 rows (4 packed pairs) x 4 channels per thread
__device__ __forceinline__ void gemm1_core(const float4* xs4, const float4* w4,
                                           int ri, int ci,
                                           u64 aL0[4], u64 aL1[4],
                                           u64 aR0[4], u64 aR1[4]) {
    const int rb0 = 2 * ri, rb1 = 2 * ri + 1;
    #pragma unroll
    for (int q = 0; q < 4; q++) { aL0[q]=0ull; aL1[q]=0ull; aR0[q]=0ull; aR1[q]=0ull; }
    #pragma unroll 1
    for (int k0 = 0; k0 < 64; k0 += 16) {
        #pragma unroll
        for (int j = 0; j < 16; j++) {
            const int k = k0 + j;
            ulonglong2 xA = *(const ulonglong2*)(xs4 + k * 16 + (rb0 ^ j));
            ulonglong2 xB = *(const ulonglong2*)(xs4 + k * 16 + (rb1 ^ j));
            float4 wv = w4[k * 32 + ci];
            u64 wl0 = pk2(wv.x, wv.x), wl1 = pk2(wv.y, wv.y);
            u64 wr0 = pk2(wv.z, wv.z), wr1 = pk2(wv.w, wv.w);
            ffma2(aL0[0], xA.x, wl0); ffma2(aL0[1], xA.y, wl0);
            ffma2(aL0[2], xB.x, wl0); ffma2(aL0[3], xB.y, wl0);
            ffma2(aL1[0], xA.x, wl1); ffma2(aL1[1], xA.y, wl1);
            ffma2(aL1[2], xB.x, wl1); ffma2(aL1[3], xB.y, wl1);
            ffma2(aR0[0], xA.x, wr0); ffma2(aR0[1], xA.y, wr0);
            ffma2(aR0[2], xB.x, wr0); ffma2(aR0[3], xB.y, wr0);
            ffma2(aR1[0], xA.x, wr1); ffma2(aR1[1], xA.y, wr1);
            ffma2(aR1[2], xB.x, wr1); ffma2(aR1[3], xB.y, wr1);
        }
    }
}

__device__ __forceinline__ void build_w1i(float4* W1i4, const float* __restrict__ W1, int tid) {
    #pragma unroll
    for (int p = 0; p < 8; p++) {
        int idx = tid + p * 256;
        int k = idx >> 5, cc = idx & 31;
        float2 l = *(const float2*)(W1 + k * 128 + 2 * cc);
        float2 r = *(const float2*)(W1 + k * 128 + 64 + 2 * cc);
        W1i4[idx] = make_float4(l.x, l.y, r.x, r.y);
    }
}

// ============================================================================
// k1: GEMM1 + gate -> g_ab (fp16 packed) + per-64-row-chunk aggregates (fp32)
// ============================================================================
__global__ __launch_bounds__(256, 3)
void k1_gemm1(const float* __restrict__ inp,
              const float* __restrict__ W1,
              const float* __restrict__ B1) {
    extern __shared__ float sm[];
    float4* W1i4  = (float4*)sm;                 // [0,32768)
    float*  xsf   = sm + 8192;                   // [32768,49152)
    float2* parts = (float2*)(sm + 12288);       // [49152,53248)

    const int tid = threadIdx.x, c = blockIdx.x;
    const int ri = tid >> 5, ci = tid & 31;

    build_w1i(W1i4, W1, tid);
    const float bl0 = B1[2 * ci],      bl1 = B1[2 * ci + 1];
    const float br0 = B1[64 + 2 * ci], br1 = B1[64 + 2 * ci + 1];
    __syncthreads();

    #pragma unroll 1
    for (int tt = 0; tt < 2; tt++) {
        const int chunk = 2 * c + tt;
        const int t0 = chunk * TILE_R;
        fill_x(xsf, inp, t0, tid);
        __syncthreads();

        u64 aL0[4], aL1[4], aR0[4], aR1[4];
        gemm1_core((const float4*)xsf, W1i4, ri, ci, aL0, aL1, aR0, aR1);

        float A0 = 1.f, B0 = 0.f, A1 = 1.f, B1v = 0.f;
        #pragma unroll
        for (int p2 = 0; p2 < 4; p2++) {
            float2 L0 = upk(aL0[p2]), L1 = upk(aL1[p2]);
            float2 R0 = upk(aR0[p2]), R1 = upk(aR1[p2]);
            #pragma unroll
            for (int e = 0; e < 2; e++) {
                int r = 8 * ri + 2 * p2 + e;
                float l0 = sigf((e ? L0.y : L0.x) + bl0);
                float l1 = sigf((e ? L1.y : L1.x) + bl1);
                float r0 = sigf((e ? R0.y : R0.x) + br0);
                float r1 = sigf((e ? R1.y : R1.x) + br1);
                float a0 = l0 * r0, b0 = 1.f - l0;
                float a1 = l1 * r1, b1 = 1.f - l1;
                g_ab[(size_t)(t0 + r) * 32 + ci] =
                    make_uint2(packh2(a0, a1), packh2(b0, b1));
                B0  = fmaf(a0, B0, b0);  A0 *= a0;
                B1v = fmaf(a1, B1v, b1); A1 *= a1;
            }
        }
        ((float4*)parts)[ri * 32 + ci] = make_float4(A0, B0, A1, B1v);
        __syncthreads();

        if (tid < 64) {
            float Ac = 1.f, Bc = 0.f;
            #pragma unroll
            for (int g = 0; g < 8; g++) {
                float2 pp = parts[g * 64 + tid];
                Bc = fmaf(pp.x, Bc, pp.y);
                Ac *= pp.x;
            }
            g_Ac[chunk * 64 + tid] = Ac;
            g_Bc[chunk * 64 + tid] = Bc;
        }
        __syncthreads();
    }
}

// ============================================================================
// k2a: super aggregates — 4 segments x 64 channels per CTA, prefetched
// ============================================================================
__global__ __launch_bounds__(256, 8)
void k2a_super_agg() {
    __shared__ float2 parts[4 * 64];
    const int s = blockIdx.x;
    const int j = threadIdx.x & 63, seg = threadIdx.x >> 6;
    const int base = s * SUPER + seg * SEGC;

    float A = 1.f, B = 0.f;
    #pragma unroll 1
    for (int bq = 0; bq < SEGC / 8; bq++) {
        float a_[8], b_[8];
        #pragma unroll
        for (int i = 0; i < 8; i++) {
            a_[i] = g_Ac[(base + bq * 8 + i) * 64 + j];
            b_[i] = g_Bc[(base + bq * 8 + i) * 64 + j];
        }
        #pragma unroll
        for (int i = 0; i < 8; i++) { B = fmaf(a_[i], B, b_[i]); A *= a_[i]; }
    }
    parts[seg * 64 + j] = make_float2(A, B);
    __syncthreads();

    if (threadIdx.x < 64) {
        float As = 1.f, Bs = 0.f;
        #pragma unroll
        for (int g = 0; g < 4; g++) {
            float2 pp = parts[g * 64 + threadIdx.x];
            Bs = fmaf(pp.x, Bs, pp.y);
            As *= pp.x;
        }
        g_A2[s * 64 + threadIdx.x] = As;
        g_B2[s * 64 + threadIdx.x] = Bs;
    }
}

// ============================================================================
// k2c: super-scan (redundant per CTA) + expand to chunk starts (merged k2b)
// ============================================================================
__global__ __launch_bounds__(256, 8)
void k2c_expand() {
    __shared__ float2 parts[4 * 64];
    __shared__ float  segu [4 * 64];
    __shared__ float  supu [64];
    const int s = blockIdx.x;
    const int j = threadIdx.x & 63, seg = threadIdx.x >> 6;
    const int base = s * SUPER + seg * SEGC;

    // phase 0 (threads 0..63): super-start state = fold of supers 0..s-1
    if (threadIdx.x < 64) {
        float u = 0.f;
        #pragma unroll 1
        for (int s0 = 0; s0 < NSUPER; s0 += 16) {
            float A_[16], B_[16];
            #pragma unroll
            for (int i = 0; i < 16; i++) {
                int sp = s0 + i;
                float a = g_A2[sp * 64 + threadIdx.x];
                float b = g_B2[sp * 64 + threadIdx.x];
                A_[i] = (sp < s) ? a : 1.f;
                B_[i] = (sp < s) ? b : 0.f;
            }
            #pragma unroll
            for (int i = 0; i < 16; i++) { u = fmaf(A_[i], u, B_[i]); }
        }
        supu[threadIdx.x] = u;
    }

    // phase 1: segment aggregates
    float A = 1.f, B = 0.f;
    #pragma unroll 1
    for (int bq = 0; bq < SEGC / 8; bq++) {
        float a_[8], b_[8];
        #pragma unroll
        for (int i = 0; i < 8; i++) {
            a_[i] = g_Ac[(base + bq * 8 + i) * 64 + j];
            b_[i] = g_Bc[(base + bq * 8 + i) * 64 + j];
        }
        #pragma unroll
        for (int i = 0; i < 8; i++) { B = fmaf(a_[i], B, b_[i]); A *= a_[i]; }
    }
    parts[seg * 64 + j] = make_float2(A, B);
    __syncthreads();

    // phase 2: segment-start states from super-start
    if (threadIdx.x < 64) {
        float u = supu[threadIdx.x];
        #pragma unroll
        for (int g = 0; g < 4; g++) {
            segu[g * 64 + threadIdx.x] = u;
            float2 pp = parts[g * 64 + threadIdx.x];
            u = fmaf(pp.x, u, pp.y);
        }
    }
    __syncthreads();

    // phase 3: expand within segment
    float u = segu[seg * 64 + j];
    #pragma unroll 1
    for (int bq = 0; bq < SEGC / 8; bq++) {
        float a_[8], b_[8];
        #pragma unroll
        for (int i = 0; i < 8; i++) {
            a_[i] = g_Ac[(base + bq * 8 + i) * 64 + j];
            b_[i] = g_Bc[(base + bq * 8 + i) * 64 + j];
        }
        #pragma unroll
        for (int i = 0; i < 8; i++) {
            g_U[(base + bq * 8 + i) * 64 + j] = u;
            u = fmaf(a_[i], u, b_[i]);
        }
    }
}

// ============================================================================
// k3: replay + GEMM2 with 8-row x 2-oc thread tile (4 active warps in GEMM2)
// ============================================================================
__global__ __launch_bounds__(256, 3)
void k3_replay_gemm2(const float* __restrict__ W2,
                     const float* __restrict__ B2,
                     float* __restrict__ out) {
    extern __shared__ float sm[];
    float*  zsf   = sm;                          // [0,16384)
    float2* parts = (float2*)(sm + 4096);        // [16384,20480)
    float*  ust   = sm + 5120;                   // [20480,22528)
    float*  W2s   = sm + 5632;                   // [22528,30720): plain float

    const int tid = threadIdx.x, c = blockIdx.x;
    const int ri = tid >> 5, ci = tid & 31;
    const int t0 = c * TILE_R;

    #pragma unroll
    for (int p = 0; p < 2; p++)          // W2s[k*32+oc] = W2[k][oc]
        ((float4*)W2s)[tid + p * 256] = ((const float4*)W2)[tid + p * 256];
    if (c == 0 && tid < 32) out[tid] = B2[tid];

    // load packed fp16 a,b for this thread's 8 rows x channel pair
    float4 ab[8];
    #pragma unroll
    for (int e = 0; e < 8; e++) {
        uint2 v = g_ab[(size_t)(t0 + 8 * ri + e) * 32 + ci];
        float2 aa = unpackh2(v.x);
        float2 bb = unpackh2(v.y);
        ab[e] = make_float4(aa.x, aa.y, bb.x, bb.y);
    }

    float A0 = 1.f, B0 = 0.f, A1 = 1.f, B1v = 0.f;
    #pragma unroll
    for (int e = 0; e < 8; e++) {
        B0  = fmaf(ab[e].x, B0,  ab[e].z);  A0 *= ab[e].x;
        B1v = fmaf(ab[e].y, B1v, ab[e].w);  A1 *= ab[e].y;
    }
    ((float4*)parts)[ri * 32 + ci] = make_float4(A0, B0, A1, B1v);
    __syncthreads();

    if (tid < 64) {
        float u = g_U[c * 64 + tid];
        #pragma unroll
        for (int g = 0; g < 8; g++) {
            ust[g * 64 + tid] = u;
            float2 pp = parts[g * 64 + tid];
            u = fmaf(pp.x, u, pp.y);
        }
    }
    __syncthreads();

    // register replay -> swizzled z tile, paired row stores (STS.64)
    {
        float2 us = *(const float2*)(ust + ri * 64 + 2 * ci);
        float u0 = us.x, u1 = us.y;
        const int j0 = 2 * ci, j1 = 2 * ci + 1;
        #pragma unroll
        for (int p = 0; p < 4; p++) {
            float a0 = fmaf(ab[2*p].x,   u0, ab[2*p].z);
            float a1 = fmaf(ab[2*p].y,   u1, ab[2*p].w);
            float c0 = fmaf(ab[2*p+1].x, a0, ab[2*p+1].z);
            float c1 = fmaf(ab[2*p+1].y, a1, ab[2*p+1].w);
            u0 = c0; u1 = c1;
            int r = 8 * ri + 2 * p;                        // r&3 in {0,2}
            int rb = r >> 2, r3 = r & 3;
            *(u64*)(zsf + (j0 * 16 + (rb ^ (j0 & 15))) * 4 + r3) = pk2(a0, c0);
            *(u64*)(zsf + (j1 * 16 + (rb ^ (j1 & 15))) * 4 + r3) = pk2(a1, c1);
        }
    }
    __syncthreads();

    // GEMM2: 8 rows x 2 out channels per thread; 128 active threads (4 warps)
    if (tid < 128) {
        const int rp2 = tid >> 4;        // row group: rows 8*rp2 .. 8*rp2+7
        const int op  = tid & 15;        // out-channel pair: 2op, 2op+1
        const float2 b2v = *(const float2*)(B2 + 2 * op);
        u64 acc0[4], acc1[4];
        #pragma unroll
        for (int p = 0; p < 4; p++) {
            acc0[p] = pk2(b2v.x, b2v.x);
            acc1[p] = pk2(b2v.y, b2v.y);
        }
        const int rb0 = 2 * rp2, rb1 = 2 * rp2 + 1;
        const float4* zs4 = (const float4*)zsf;
        #pragma unroll 1
        for (int k0 = 0; k0 < 64; k0 += 16) {
            #pragma unroll
            for (int j = 0; j < 16; j++) {
                const int k = k0 + j;
                ulonglong2 zA = *(const ulonglong2*)(zs4 + k * 16 + (rb0 ^ j));
                ulonglong2 zB = *(const ulonglong2*)(zs4 + k * 16 + (rb1 ^ j));
                float2 wv = *(const float2*)(W2s + k * 32 + 2 * op);
                u64 w0 = pk2(wv.x, wv.x);
                u64 w1 = pk2(wv.y, wv.y);
                ffma2(acc0[0], zA.x, w0); ffma2(acc0[1], zA.y, w0);
                ffma2(acc0[2], zB.x, w0); ffma2(acc0[3], zB.y, w0);
                ffma2(acc1[0], zA.x, w1); ffma2(acc1[1], zA.y, w1);
                ffma2(acc1[2], zB.x, w1); ffma2(acc1[3], zB.y, w1);
            }
        }
        #pragma unroll
        for (int p = 0; p < 4; p++) {
            float2 v0 = upk(acc0[p]);
            float2 v1 = upk(acc1[p]);
            int t = t0 + 1 + 8 * rp2 + 2 * p;
            if (t < T_TOTAL)
                *(float2*)(out + (size_t)t * 32 + 2 * op) = make_float2(v0.x, v1.x);
            if (t + 1 < T_TOTAL)
                *(float2*)(out + (size_t)(t + 1) * 32 + 2 * op) = make_float2(v0.y, v1.y);
        }
    }
}

// ============================================================================
// launch
// ============================================================================
extern "C" void kernel_launch(void* const* d_in, const int* in_sizes, int n_in,
                              void* d_out, int out_size) {
    const float* inp = (const float*)d_in[0];
    const float* W1  = (const float*)d_in[1];
    const float* B1  = (const float*)d_in[2];
    const float* W2  = (const float*)d_in[3];
    const float* B2  = (const float*)d_in[4];
    float* out = (float*)d_out;

    const int smem1 = 53248;
    const int smem3 = 30720;
    cudaFuncSetAttribute(k1_gemm1,        cudaFuncAttributeMaxDynamicSharedMemorySize, smem1);
    cudaFuncSetAttribute(k3_replay_gemm2, cudaFuncAttributeMaxDynamicSharedMemorySize, smem3);

    k1_gemm1<<<K1_BLK, 256, smem1>>>(inp, W1, B1);
    k2a_super_agg<<<NSUPER, 256>>>();
    k2c_expand<<<NSUPER, 256>>>();
    k3_replay_gemm2<<<NCHUNK, 256, smem3>>>(W2, B2, out);
    (void)in_sizes; (void)n_in; (void)out_size;
}

// round 17
// speedup vs baseline: 1.2119x; 1.0086x over previous
#include <cuda_runtime.h>
#include <cuda_fp16.h>
#include <cstdint>
#include <cstddef>

#define T_TOTAL 524288
#define NCHUNK  8192          // 64-row chunks
#define K1_BLK  4096          // k1: 128 rows (2 tiles) per CTA
#define TILE_R  64
#define SUPER   128           // chunks per super-chunk in k2
#define NSUPER  (NCHUNK / SUPER)
#define SEGC    32            // chunks per segment (4 segments per super)

// packed per-row gate params, fp16: {f16x2(a0,a1), f16x2(b0,b1)} -> 134MB
__device__ __align__(16) uint2 g_ab[(size_t)T_TOTAL * 32];
// per-chunk aggregates and chunk-start states (fp32 exact path)
__device__ __align__(16) float g_Ac[NCHUNK * 64];
__device__ __align__(16) float g_Bc[NCHUNK * 64];
__device__ __align__(16) float g_U [NCHUNK * 64];
__device__ __align__(16) float g_A2[NSUPER * 64];
__device__ __align__(16) float g_B2[NSUPER * 64];

typedef unsigned long long u64;

__device__ __forceinline__ u64 pk2(float lo, float hi) {
    u64 r; asm("mov.b64 %0, {%1,%2};" : "=l"(r) : "f"(lo), "f"(hi)); return r;
}
__device__ __forceinline__ float2 upk(u64 v) {
    float2 r; asm("mov.b64 {%0,%1}, %2;" : "=f"(r.x), "=f"(r.y) : "l"(v)); return r;
}
__device__ __forceinline__ void ffma2(u64 &d, u64 a, u64 b) {
    asm("fma.rn.f32x2 %0, %1, %2, %0;" : "+l"(d) : "l"(a), "l"(b));
}
// sigmoid via single-MUFU tanh: sigma(x) = 0.5*tanh(x/2) + 0.5
__device__ __forceinline__ float sigf(float x) {
    float t;
    asm("tanh.approx.f32 %0, %1;" : "=f"(t) : "f"(0.5f * x));
    return fmaf(0.5f, t, 0.5f);
}
__device__ __forceinline__ unsigned packh2(float x, float y) {
    unsigned r;
    asm("cvt.rn.f16x2.f32 %0, %2, %1;" : "=r"(r) : "f"(x), "f"(y));
    return r;
}
__device__ __forceinline__ float2 unpackh2(unsigned v) {
    float2 r;
    unsigned short lo = (unsigned short)(v & 0xFFFFu);
    unsigned short hi = (unsigned short)(v >> 16);
    asm("cvt.f32.f16 %0, %1;" : "=f"(r.x) : "h"(lo));
    asm("cvt.f32.f16 %0, %1;" : "=f"(r.y) : "h"(hi));
    return r;
}

// swizzled transposed x tile: float4 block (k, rb) at k*16 + (rb ^ (k&15))
__device__ __forceinline__ void fill_x(float* xsf, const float* __restrict__ inp,
                                       int t0, int tid) {
    #pragma unroll
    for (int p = 0; p < 4; p++) {
        int i = tid + p * 256;
        int r = i >> 4, c = i & 15;
        float4 v = *(const float4*)(inp + (size_t)(t0 + r) * 64 + 4 * c);
        int rb = r >> 2, r3 = r & 3;
        #pragma unroll
        for (int j = 0; j < 4; j++) {
            int k = 4 * c + j;
            float val = (j == 0) ? v.x : (j == 1) ? v.y : (j == 2) ? v.z : v.w;
            xsf[(k * 16 + (rb ^ (k & 15))) * 4 + r3] = val;
        }
    }
}

// GEMM1 core: 8 rows (4 packed pairs) x 4 channels per thread
__device__ __forceinline__ void gemm1_core(const float4* xs4, const float4* w4,
                                           int ri, int ci,
                                           u64 aL0[4], u64 aL1[4],
                                           u64 aR0[4], u64 aR1[4]) {
    const int rb0 = 2 * ri, rb1 = 2 * ri + 1;
    #pragma unroll
    for (int q = 0; q < 4; q++) { aL0[q]=0ull; aL1[q]=0ull; aR0[q]=0ull; aR1[q]=0ull; }
    #pragma unroll 1
    for (int k0 = 0; k0 < 64; k0 += 16) {
        #pragma unroll
        for (int j = 0; j < 16; j++) {
            const int k = k0 + j;
            ulonglong2 xA = *(const ulonglong2*)(xs4 + k * 16 + (rb0 ^ j));
            ulonglong2 xB = *(const ulonglong2*)(xs4 + k * 16 + (rb1 ^ j));
            float4 wv = w4[k * 32 + ci];
            u64 wl0 = pk2(wv.x, wv.x), wl1 = pk2(wv.y, wv.y);
            u64 wr0 = pk2(wv.z, wv.z), wr1 = pk2(wv.w, wv.w);
            ffma2(aL0[0], xA.x, wl0); ffma2(aL0[1], xA.y, wl0);
            ffma2(aL0[2], xB.x, wl0); ffma2(aL0[3], xB.y, wl0);
            ffma2(aL1[0], xA.x, wl1); ffma2(aL1[1], xA.y, wl1);
            ffma2(aL1[2], xB.x, wl1); ffma2(aL1[3], xB.y, wl1);
            ffma2(aR0[0], xA.x, wr0); ffma2(aR0[1], xA.y, wr0);
            ffma2(aR0[2], xB.x, wr0); ffma2(aR0[3], xB.y, wr0);
            ffma2(aR1[0], xA.x, wr1); ffma2(aR1[1], xA.y, wr1);
            ffma2(aR1[2], xB.x, wr1); ffma2(aR1[3], xB.y, wr1);
        }
    }
}

__device__ __forceinline__ void build_w1i(float4* W1i4, const float* __restrict__ W1, int tid) {
    #pragma unroll
    for (int p = 0; p < 8; p++) {
        int idx = tid + p * 256;
        int k = idx >> 5, cc = idx & 31;
        float2 l = *(const float2*)(W1 + k * 128 + 2 * cc);
        float2 r = *(const float2*)(W1 + k * 128 + 64 + 2 * cc);
        W1i4[idx] = make_float4(l.x, l.y, r.x, r.y);
    }
}

// ============================================================================
// k1: GEMM1 + gate -> g_ab (fp16 packed) + per-chunk aggregates
// both x tiles prefetched upfront (double-buffered); tanh-based sigmoid
// smem = 69632 B, 3 CTAs/SM
// ============================================================================
__global__ __launch_bounds__(256, 3)
void k1_gemm1(const float* __restrict__ inp,
              const float* __restrict__ W1,
              const float* __restrict__ B1) {
    extern __shared__ float sm[];
    float4* W1i4  = (float4*)sm;                 // [0,32768)
    float*  xsfA  = sm + 8192;                   // [32768,49152)
    float*  xsfB  = sm + 12288;                  // [49152,65536)
    float2* parts = (float2*)(sm + 16384);       // [65536,69632)

    const int tid = threadIdx.x, c = blockIdx.x;
    const int ri = tid >> 5, ci = tid & 31;

    build_w1i(W1i4, W1, tid);
    const float bl0 = B1[2 * ci],      bl1 = B1[2 * ci + 1];
    const float br0 = B1[64 + 2 * ci], br1 = B1[64 + 2 * ci + 1];

    // prefetch both tiles (high MLP, one exposed latency)
    fill_x(xsfA, inp, (2 * c)     * TILE_R, tid);
    fill_x(xsfB, inp, (2 * c + 1) * TILE_R, tid);
    __syncthreads();

    #pragma unroll 1
    for (int tt = 0; tt < 2; tt++) {
        const int chunk = 2 * c + tt;
        const int t0 = chunk * TILE_R;
        const float* xsf = tt ? xsfB : xsfA;

        u64 aL0[4], aL1[4], aR0[4], aR1[4];
        gemm1_core((const float4*)xsf, W1i4, ri, ci, aL0, aL1, aR0, aR1);

        float A0 = 1.f, B0 = 0.f, A1 = 1.f, B1v = 0.f;
        #pragma unroll
        for (int p2 = 0; p2 < 4; p2++) {
            float2 L0 = upk(aL0[p2]), L1 = upk(aL1[p2]);
            float2 R0 = upk(aR0[p2]), R1 = upk(aR1[p2]);
            #pragma unroll
            for (int e = 0; e < 2; e++) {
                int r = 8 * ri + 2 * p2 + e;
                float l0 = sigf((e ? L0.y : L0.x) + bl0);
                float l1 = sigf((e ? L1.y : L1.x) + bl1);
                float r0 = sigf((e ? R0.y : R0.x) + br0);
                float r1 = sigf((e ? R1.y : R1.x) + br1);
                float a0 = l0 * r0, b0 = 1.f - l0;
                float a1 = l1 * r1, b1 = 1.f - l1;
                g_ab[(size_t)(t0 + r) * 32 + ci] =
                    make_uint2(packh2(a0, a1), packh2(b0, b1));
                B0  = fmaf(a0, B0, b0);  A0 *= a0;
                B1v = fmaf(a1, B1v, b1); A1 *= a1;
            }
        }
        ((float4*)parts)[ri * 32 + ci] = make_float4(A0, B0, A1, B1v);
        __syncthreads();

        if (tid < 64) {
            float Ac = 1.f, Bc = 0.f;
            #pragma unroll
            for (int g = 0; g < 8; g++) {
                float2 pp = parts[g * 64 + tid];
                Bc = fmaf(pp.x, Bc, pp.y);
                Ac *= pp.x;
            }
            g_Ac[chunk * 64 + tid] = Ac;
            g_Bc[chunk * 64 + tid] = Bc;
        }
        __syncthreads();   // parts reuse by next tile
    }
}

// ============================================================================
// k2a: super aggregates — 4 segments x 64 channels per CTA, prefetched
// ============================================================================
__global__ __launch_bounds__(256, 8)
void k2a_super_agg() {
    __shared__ float2 parts[4 * 64];
    const int s = blockIdx.x;
    const int j = threadIdx.x & 63, seg = threadIdx.x >> 6;
    const int base = s * SUPER + seg * SEGC;

    float A = 1.f, B = 0.f;
    #pragma unroll 1
    for (int bq = 0; bq < SEGC / 8; bq++) {
        float a_[8], b_[8];
        #pragma unroll
        for (int i = 0; i < 8; i++) {
            a_[i] = g_Ac[(base + bq * 8 + i) * 64 + j];
            b_[i] = g_Bc[(base + bq * 8 + i) * 64 + j];
        }
        #pragma unroll
        for (int i = 0; i < 8; i++) { B = fmaf(a_[i], B, b_[i]); A *= a_[i]; }
    }
    parts[seg * 64 + j] = make_float2(A, B);
    __syncthreads();

    if (threadIdx.x < 64) {
        float As = 1.f, Bs = 0.f;
        #pragma unroll
        for (int g = 0; g < 4; g++) {
            float2 pp = parts[g * 64 + threadIdx.x];
            Bs = fmaf(pp.x, Bs, pp.y);
            As *= pp.x;
        }
        g_A2[s * 64 + threadIdx.x] = As;
        g_B2[s * 64 + threadIdx.x] = Bs;
    }
}

// ============================================================================
// k2c: super-scan (redundant per CTA) + expand to chunk starts (merged k2b)
// ============================================================================
__global__ __launch_bounds__(256, 8)
void k2c_expand() {
    __shared__ float2 parts[4 * 64];
    __shared__ float  segu [4 * 64];
    __shared__ float  supu [64];
    const int s = blockIdx.x;
    const int j = threadIdx.x & 63, seg = threadIdx.x >> 6;
    const int base = s * SUPER + seg * SEGC;

    // phase 0 (threads 0..63): super-start state = fold of supers 0..s-1
    if (threadIdx.x < 64) {
        float u = 0.f;
        #pragma unroll 1
        for (int s0 = 0; s0 < NSUPER; s0 += 16) {
            float A_[16], B_[16];
            #pragma unroll
            for (int i = 0; i < 16; i++) {
                int sp = s0 + i;
                float a = g_A2[sp * 64 + threadIdx.x];
                float b = g_B2[sp * 64 + threadIdx.x];
                A_[i] = (sp < s) ? a : 1.f;
                B_[i] = (sp < s) ? b : 0.f;
            }
            #pragma unroll
            for (int i = 0; i < 16; i++) { u = fmaf(A_[i], u, B_[i]); }
        }
        supu[threadIdx.x] = u;
    }

    // phase 1: segment aggregates
    float A = 1.f, B = 0.f;
    #pragma unroll 1
    for (int bq = 0; bq < SEGC / 8; bq++) {
        float a_[8], b_[8];
        #pragma unroll
        for (int i = 0; i < 8; i++) {
            a_[i] = g_Ac[(base + bq * 8 + i) * 64 + j];
            b_[i] = g_Bc[(base + bq * 8 + i) * 64 + j];
        }
        #pragma unroll
        for (int i = 0; i < 8; i++) { B = fmaf(a_[i], B, b_[i]); A *= a_[i]; }
    }
    parts[seg * 64 + j] = make_float2(A, B);
    __syncthreads();

    // phase 2: segment-start states from super-start
    if (threadIdx.x < 64) {
        float u = supu[threadIdx.x];
        #pragma unroll
        for (int g = 0; g < 4; g++) {
            segu[g * 64 + threadIdx.x] = u;
            float2 pp = parts[g * 64 + threadIdx.x];
            u = fmaf(pp.x, u, pp.y);
        }
    }
    __syncthreads();

    // phase 3: expand within segment
    float u = segu[seg * 64 + j];
    #pragma unroll 1
    for (int bq = 0; bq < SEGC / 8; bq++) {
        float a_[8], b_[8];
        #pragma unroll
        for (int i = 0; i < 8; i++) {
            a_[i] = g_Ac[(base + bq * 8 + i) * 64 + j];
            b_[i] = g_Bc[(base + bq * 8 + i) * 64 + j];
        }
        #pragma unroll
        for (int i = 0; i < 8; i++) {
            g_U[(base + bq * 8 + i) * 64 + j] = u;
            u = fmaf(a_[i], u, b_[i]);
        }
    }
}

// ============================================================================
// k3: replay + GEMM2 with 8-row x 2-oc thread tile (4 active warps in GEMM2)
// ============================================================================
__global__ __launch_bounds__(256, 3)
void k3_replay_gemm2(const float* __restrict__ W2,
                     const float* __restrict__ B2,
                     float* __restrict__ out) {
    extern __shared__ float sm[];
    float*  zsf   = sm;                          // [0,16384)
    float2* parts = (float2*)(sm + 4096);        // [16384,20480)
    float*  ust   = sm + 5120;                   // [20480,22528)
    float*  W2s   = sm + 5632;                   // [22528,30720): plain float

    const int tid = threadIdx.x, c = blockIdx.x;
    const int ri = tid >> 5, ci = tid & 31;
    const int t0 = c * TILE_R;

    #pragma unroll
    for (int p = 0; p < 2; p++)          // W2s[k*32+oc] = W2[k][oc]
        ((float4*)W2s)[tid + p * 256] = ((const float4*)W2)[tid + p * 256];
    if (c == 0 && tid < 32) out[tid] = B2[tid];

    // load packed fp16 a,b for this thread's 8 rows x channel pair
    float4 ab[8];
    #pragma unroll
    for (int e = 0; e < 8; e++) {
        uint2 v = g_ab[(size_t)(t0 + 8 * ri + e) * 32 + ci];
        float2 aa = unpackh2(v.x);
        float2 bb = unpackh2(v.y);
        ab[e] = make_float4(aa.x, aa.y, bb.x, bb.y);
    }

    float A0 = 1.f, B0 = 0.f, A1 = 1.f, B1v = 0.f;
    #pragma unroll
    for (int e = 0; e < 8; e++) {
        B0  = fmaf(ab[e].x, B0,  ab[e].z);  A0 *= ab[e].x;
        B1v = fmaf(ab[e].y, B1v, ab[e].w);  A1 *= ab[e].y;
    }
    ((float4*)parts)[ri * 32 + ci] = make_float4(A0, B0, A1, B1v);
    __syncthreads();

    if (tid < 64) {
        float u = g_U[c * 64 + tid];
        #pragma unroll
        for (int g = 0; g < 8; g++) {
            ust[g * 64 + tid] = u;
            float2 pp = parts[g * 64 + tid];
            u = fmaf(pp.x, u, pp.y);
        }
    }
    __syncthreads();

    // register replay -> swizzled z tile, paired row stores (STS.64)
    {
        float2 us = *(const float2*)(ust + ri * 64 + 2 * ci);
        float u0 = us.x, u1 = us.y;
        const int j0 = 2 * ci, j1 = 2 * ci + 1;
        #pragma unroll
        for (int p = 0; p < 4; p++) {
            float a0 = fmaf(ab[2*p].x,   u0, ab[2*p].z);
            float a1 = fmaf(ab[2*p].y,   u1, ab[2*p].w);
            float c0 = fmaf(ab[2*p+1].x, a0, ab[2*p+1].z);
            float c1 = fmaf(ab[2*p+1].y, a1, ab[2*p+1].w);
            u0 = c0; u1 = c1;
            int r = 8 * ri + 2 * p;                        // r&3 in {0,2}
            int rb = r >> 2, r3 = r & 3;
            *(u64*)(zsf + (j0 * 16 + (rb ^ (j0 & 15))) * 4 + r3) = pk2(a0, c0);
            *(u64*)(zsf + (j1 * 16 + (rb ^ (j1 & 15))) * 4 + r3) = pk2(a1, c1);
        }
    }
    __syncthreads();

    // GEMM2: 8 rows x 2 out channels per thread; 128 active threads (4 warps)
    if (tid < 128) {
        const int rp2 = tid >> 4;        // row group: rows 8*rp2 .. 8*rp2+7
        const int op  = tid & 15;        // out-channel pair: 2op, 2op+1
        const float2 b2v = *(const float2*)(B2 + 2 * op);
        u64 acc0[4], acc1[4];
        #pragma unroll
        for (int p = 0; p < 4; p++) {
            acc0[p] = pk2(b2v.x, b2v.x);
            acc1[p] = pk2(b2v.y, b2v.y);
        }
        const int rb0 = 2 * rp2, rb1 = 2 * rp2 + 1;
        const float4* zs4 = (const float4*)zsf;
        #pragma unroll 1
        for (int k0 = 0; k0 < 64; k0 += 16) {
            #pragma unroll
            for (int j = 0; j < 16; j++) {
                const int k = k0 + j;
                ulonglong2 zA = *(const ulonglong2*)(zs4 + k * 16 + (rb0 ^ j));
                ulonglong2 zB = *(const ulonglong2*)(zs4 + k * 16 + (rb1 ^ j));
                float2 wv = *(const float2*)(W2s + k * 32 + 2 * op);
                u64 w0 = pk2(wv.x, wv.x);
                u64 w1 = pk2(wv.y, wv.y);
                ffma2(acc0[0], zA.x, w0); ffma2(acc0[1], zA.y, w0);
                ffma2(acc0[2], zB.x, w0); ffma2(acc0[3], zB.y, w0);
                ffma2(acc1[0], zA.x, w1); ffma2(acc1[1], zA.y, w1);
                ffma2(acc1[2], zB.x, w1); ffma2(acc1[3], zB.y, w1);
            }
        }
        #pragma unroll
        for (int p = 0; p < 4; p++) {
            float2 v0 = upk(acc0[p]);
            float2 v1 = upk(acc1[p]);
            int t = t0 + 1 + 8 * rp2 + 2 * p;
            if (t < T_TOTAL)
                *(float2*)(out + (size_t)t * 32 + 2 * op) = make_float2(v0.x, v1.x);
            if (t + 1 < T_TOTAL)
                *(float2*)(out + (size_t)(t + 1) * 32 + 2 * op) = make_float2(v0.y, v1.y);
        }
    }
}

// ============================================================================
// launch
// ============================================================================
extern "C" void kernel_launch(void* const* d_in, const int* in_sizes, int n_in,
                              void* d_out, int out_size) {
    const float* inp = (const float*)d_in[0];
    const float* W1  = (const float*)d_in[1];
    const float* B1  = (const float*)d_in[2];
    const float* W2  = (const float*)d_in[3];
    const float* B2  = (const float*)d_in[4];
    float* out = (float*)d_out;

    const int smem1 = 69632;
    const int smem3 = 30720;
    cudaFuncSetAttribute(k1_gemm1,        cudaFuncAttributeMaxDynamicSharedMemorySize, smem1);
    cudaFuncSetAttribute(k3_replay_gemm2, cudaFuncAttributeMaxDynamicSharedMemorySize, smem3);

    k1_gemm1<<<K1_BLK, 256, smem1>>>(inp, W1, B1);
    k2a_super_agg<<<NSUPER, 256>>>();
    k2c_expand<<<NSUPER, 256>>>();
    k3_replay_gemm2<<<NCHUNK, 256, smem3>>>(W2, B2, out);
    (void)in_sizes; (void)n_in; (void)out_size;
}